// round 2
// baseline (speedup 1.0000x reference)
#include <cuda_runtime.h>
#include <cstdint>
#include <cstddef>

// Problem constants (fixed by the dataset)
#define NR    16384
#define NCH   65536
#define NP    16384
#define DIM   64
#define ERC   65536
#define EPASS 65536
#define EN    2048   // D*D/2

// Device scratch (allocation-free rule: __device__ globals)
__device__ float g_e   [(size_t)NP  * EN];   // 128 MB: per-packet message matrices
__device__ float g_hin [(size_t)NCH * DIM];  // 16 MB
__device__ float g_hout[(size_t)NCH * DIM];  // 16 MB
__device__ float g_min [(size_t)NCH * 32];   // 8 MB
__device__ float g_mout[(size_t)NCH * 32];   // 8 MB

__device__ __forceinline__ void red_add_v4(float* p, float4 v) {
    asm volatile("red.global.add.v4.f32 [%0], {%1,%2,%3,%4};"
                 :: "l"(p), "f"(v.x), "f"(v.y), "f"(v.z), "f"(v.w) : "memory");
}
__device__ __forceinline__ void red_add_f(float* p, float v) {
    asm volatile("red.global.add.f32 [%0], %1;" :: "l"(p), "f"(v) : "memory");
}

// ---------------------------------------------------------------------------
// K0: zero hin/hout/min/mout/out in one grid-stride launch
__global__ void zero_all_kernel(float4* __restrict__ hin, float4* __restrict__ hout,
                                float4* __restrict__ min_, float4* __restrict__ mout_,
                                float4* __restrict__ out) {
    const int n_h = (NCH * DIM) / 4;   // 1M float4
    const int n_m = (NCH * 32) / 4;    // 512K float4
    const int n_o = (NR * DIM) / 4;    // 256K float4
    float4 z = make_float4(0.f, 0.f, 0.f, 0.f);
    int stride = gridDim.x * blockDim.x;
    for (int i = blockIdx.x * blockDim.x + threadIdx.x; i < n_h; i += stride) {
        hin[i] = z; hout[i] = z;
    }
    for (int i = blockIdx.x * blockDim.x + threadIdx.x; i < n_m; i += stride) {
        min_[i] = z; mout_[i] = z;
    }
    for (int i = blockIdx.x * blockDim.x + threadIdx.x; i < n_o; i += stride) {
        out[i] = z;
    }
}

// ---------------------------------------------------------------------------
// K1: scatter-add h rows along edges: acc[dst[e]] += h[src[e]]  (64 floats/row)
// one thread per (edge, float4-chunk): 16 chunks per edge. Two edge lists in
// one launch (hin via list0, hout via list1).
__global__ void scatter_h_kernel(const int* __restrict__ src0, const int* __restrict__ dst0,
                                 const int* __restrict__ src1, const int* __restrict__ dst1,
                                 const float* __restrict__ h,
                                 float* __restrict__ acc0, float* __restrict__ acc1) {
    int tid = blockIdx.x * blockDim.x + threadIdx.x;
    int e = tid >> 4;
    int c = tid & 15;
    const int* src; const int* dst; float* acc;
    if (e < ERC) { src = src0; dst = dst0; acc = acc0; }
    else if (e < 2 * ERC) { e -= ERC; src = src1; dst = dst1; acc = acc1; }
    else return;
    int s = src[e];
    int d = dst[e];
    float4 v = *(const float4*)(h + (size_t)s * DIM + c * 4);
    red_add_v4(acc + (size_t)d * DIM + c * 4, v);
}

// ---------------------------------------------------------------------------
// K2: e = h_packet @ W_p^T + b_p   (M=16384, N=2048, K=64)
// 128x128 tile, 256 threads, 8x8 per thread (split 4+4 in each dim for
// conflict-free float4 smem reads). Full K in one shot.
__global__ void gemm_e_kernel(const float* __restrict__ A,   // [NP, 64]
                              const float* __restrict__ B,   // [EN, 64]
                              const float* __restrict__ bias,// [EN]
                              float* __restrict__ C) {       // [NP, EN]
    extern __shared__ float sm[];
    float (*As)[128] = (float (*)[128])sm;              // [64][128] k-major
    float (*Bs)[128] = (float (*)[128])(sm + 64 * 128);

    const int t  = threadIdx.x;
    const int m0 = blockIdx.y * 128;
    const int n0 = blockIdx.x * 128;

#pragma unroll
    for (int i = 0; i < 8; i++) {
        int idx = i * 256 + t;       // 0..2047
        int r   = idx & 127;         // row within tile
        int k4  = idx >> 7;          // 0..15
        float4 va = *(const float4*)(A + (size_t)(m0 + r) * DIM + k4 * 4);
        As[k4*4+0][r] = va.x; As[k4*4+1][r] = va.y;
        As[k4*4+2][r] = va.z; As[k4*4+3][r] = va.w;
        float4 vb = *(const float4*)(B + (size_t)(n0 + r) * DIM + k4 * 4);
        Bs[k4*4+0][r] = vb.x; Bs[k4*4+1][r] = vb.y;
        Bs[k4*4+2][r] = vb.z; Bs[k4*4+3][r] = vb.w;
    }
    __syncthreads();

    const int tx = t & 15;   // n
    const int ty = t >> 4;   // m
    float acc[8][8];
#pragma unroll
    for (int i = 0; i < 8; i++)
#pragma unroll
        for (int j = 0; j < 8; j++) acc[i][j] = 0.f;

#pragma unroll 16
    for (int k = 0; k < 64; k++) {
        float4 a0 = *(const float4*)&As[k][ty * 4];
        float4 a1 = *(const float4*)&As[k][64 + ty * 4];
        float4 b0 = *(const float4*)&Bs[k][tx * 4];
        float4 b1 = *(const float4*)&Bs[k][64 + tx * 4];
        float a[8] = {a0.x, a0.y, a0.z, a0.w, a1.x, a1.y, a1.z, a1.w};
        float b[8] = {b0.x, b0.y, b0.z, b0.w, b1.x, b1.y, b1.z, b1.w};
#pragma unroll
        for (int i = 0; i < 8; i++)
#pragma unroll
            for (int j = 0; j < 8; j++) acc[i][j] += a[i] * b[j];
    }

    float4 bias0 = *(const float4*)(bias + n0 + tx * 4);
    float4 bias1 = *(const float4*)(bias + n0 + 64 + tx * 4);
#pragma unroll
    for (int i = 0; i < 8; i++) {
        int m = m0 + ((i < 4) ? (ty * 4 + i) : (64 + ty * 4 + (i - 4)));
        float* cp = C + (size_t)m * EN + n0;
        float4 v0 = make_float4(acc[i][0] + bias0.x, acc[i][1] + bias0.y,
                                acc[i][2] + bias0.z, acc[i][3] + bias0.w);
        float4 v1 = make_float4(acc[i][4] + bias1.x, acc[i][5] + bias1.y,
                                acc[i][6] + bias1.z, acc[i][7] + bias1.w);
        *(float4*)(cp + tx * 4)      = v0;
        *(float4*)(cp + 64 + tx * 4) = v1;
    }
}

// ---------------------------------------------------------------------------
// K3: pass edges. One warp per edge (u=pass_src packet, v=pass_dst channel):
//   m_in[v,k]  += sum_d e[u, d*32+k] * h_in[v,d]
//   m_out[v,k] += sum_d e[u, d*32+k] * h_out[v,d]
// lane = k (coalesced e reads), h broadcast via shfl.
__global__ void pass_kernel(const int* __restrict__ psrc, const int* __restrict__ pdst,
                            const float* __restrict__ e,
                            const float* __restrict__ hin, const float* __restrict__ hout,
                            float* __restrict__ min_, float* __restrict__ mout_) {
    int gtid = blockIdx.x * blockDim.x + threadIdx.x;
    int w    = gtid >> 5;
    int lane = gtid & 31;
    if (w >= EPASS) return;
    int u = psrc[w];
    int v = pdst[w];

    const float* ev = e + (size_t)u * EN + lane;
    float hi0 = hin [(size_t)v * DIM + lane];
    float hi1 = hin [(size_t)v * DIM + 32 + lane];
    float ho0 = hout[(size_t)v * DIM + lane];
    float ho1 = hout[(size_t)v * DIM + 32 + lane];

    float mi = 0.f, mo = 0.f;
#pragma unroll
    for (int d = 0; d < 32; d++) {
        float ed = ev[d * 32];
        mi += ed * __shfl_sync(0xffffffffu, hi0, d);
        mo += ed * __shfl_sync(0xffffffffu, ho0, d);
    }
#pragma unroll
    for (int d = 0; d < 32; d++) {
        float ed = ev[(d + 32) * 32];
        mi += ed * __shfl_sync(0xffffffffu, hi1, d);
        mo += ed * __shfl_sync(0xffffffffu, ho1, d);
    }
    red_add_f(min_  + (size_t)v * 32 + lane, mi);
    red_add_f(mout_ + (size_t)v * 32 + lane, mo);
}

// ---------------------------------------------------------------------------
// K4: gather channel -> router into d_out (cols 0..31 from m_in via input edges,
// cols 32..63 from m_out via output_inv edges). Warp per (edge, half).
__global__ void gather_kernel(const int* __restrict__ isrc, const int* __restrict__ idst,
                              const int* __restrict__ oisrc, const int* __restrict__ oidst,
                              const float* __restrict__ min_, const float* __restrict__ mout_,
                              float* __restrict__ out) {
    int gtid = blockIdx.x * blockDim.x + threadIdx.x;
    int w    = gtid >> 5;
    int lane = gtid & 31;
    if (w < ERC) {
        int s = isrc[w], d = idst[w];
        red_add_f(out + (size_t)d * DIM + lane, min_[(size_t)s * 32 + lane]);
    } else if (w < 2 * ERC) {
        int ww = w - ERC;
        int s = oisrc[ww], d = oidst[ww];
        red_add_f(out + (size_t)d * DIM + 32 + lane, mout_[(size_t)s * 32 + lane]);
    }
}

// ---------------------------------------------------------------------------
// K5: relu epilogue on out
__global__ void relu_kernel(float4* __restrict__ out) {
    int i = blockIdx.x * blockDim.x + threadIdx.x;
    float4 v = out[i];
    v.x = fmaxf(v.x, 0.f); v.y = fmaxf(v.y, 0.f);
    v.z = fmaxf(v.z, 0.f); v.w = fmaxf(v.w, 0.f);
    out[i] = v;
}

// ===========================================================================
extern "C" void kernel_launch(void* const* d_in, const int* in_sizes, int n_in,
                              void* d_out, int out_size) {
    const float* h_router       = (const float*)d_in[0];
    const float* h_packet       = (const float*)d_in[1];
    const float* W_p            = (const float*)d_in[2];
    const float* b_p            = (const float*)d_in[3];
    // d_in[4] = W_c, d_in[5] = b_c : dead code in reference
    const int* output_src       = (const int*)d_in[6];
    const int* output_dst       = (const int*)d_in[7];
    const int* input_inv_src    = (const int*)d_in[8];
    const int* input_inv_dst    = (const int*)d_in[9];
    const int* pass_src         = (const int*)d_in[10];
    const int* pass_dst         = (const int*)d_in[11];
    const int* input_src        = (const int*)d_in[12];
    const int* input_dst        = (const int*)d_in[13];
    const int* output_inv_src   = (const int*)d_in[14];
    const int* output_inv_dst   = (const int*)d_in[15];
    float* out = (float*)d_out;

    float *p_e, *p_hin, *p_hout, *p_min, *p_mout;
    cudaGetSymbolAddress((void**)&p_e,    g_e);
    cudaGetSymbolAddress((void**)&p_hin,  g_hin);
    cudaGetSymbolAddress((void**)&p_hout, g_hout);
    cudaGetSymbolAddress((void**)&p_min,  g_min);
    cudaGetSymbolAddress((void**)&p_mout, g_mout);

    cudaFuncSetAttribute(gemm_e_kernel,
                         cudaFuncAttributeMaxDynamicSharedMemorySize, 65536);

    // zero accumulators + output (one launch)
    zero_all_kernel<<<2048, 256>>>((float4*)p_hin, (float4*)p_hout,
                                   (float4*)p_min, (float4*)p_mout, (float4*)out);

    // router -> channel scatter-adds (both edge lists, one launch)
    scatter_h_kernel<<<(2 * ERC * 16) / 256, 256>>>(
        output_src, output_dst, input_inv_src, input_inv_dst,
        h_router, p_hin, p_hout);

    // e = h_packet @ W_p^T + b_p
    {
        dim3 grid(EN / 128, NP / 128);  // (16, 128)
        gemm_e_kernel<<<grid, 256, 65536>>>(h_packet, W_p, b_p, p_e);
    }

    // pass edges: warp per edge
    pass_kernel<<<(EPASS * 32) / 256, 256>>>(pass_src, pass_dst, p_e,
                                             p_hin, p_hout, p_min, p_mout);

    // channel -> router gathers into out
    gather_kernel<<<(2 * ERC * 32) / 256, 256>>>(input_src, input_dst,
                                                 output_inv_src, output_inv_dst,
                                                 p_min, p_mout, out);

    // relu epilogue
    relu_kernel<<<(NR * DIM) / (4 * 256), 256>>>((float4*)out);
}

// round 3
// speedup vs baseline: 1.2202x; 1.2202x over previous
#include <cuda_runtime.h>
#include <cuda_fp16.h>
#include <cstdint>
#include <cstddef>

// Problem constants (fixed by the dataset)
#define NR    16384
#define NCH   65536
#define NP    16384
#define DIM   64
#define ERC   65536
#define EPASS 65536
#define EN    2048   // D*D/2

// Device scratch (allocation-free rule: __device__ globals)
__device__ __half g_e  [(size_t)NP  * EN];   // 64 MB: per-packet message matrices (fp16)
__device__ float g_hin [(size_t)NCH * DIM];  // 16 MB
__device__ float g_hout[(size_t)NCH * DIM];  // 16 MB
__device__ float g_min [(size_t)NCH * 32];   // 8 MB
__device__ float g_mout[(size_t)NCH * 32];   // 8 MB

__device__ __forceinline__ void red_add_v4(float* p, float4 v) {
    asm volatile("red.global.add.v4.f32 [%0], {%1,%2,%3,%4};"
                 :: "l"(p), "f"(v.x), "f"(v.y), "f"(v.z), "f"(v.w) : "memory");
}
__device__ __forceinline__ void red_add_v2(float* p, float x, float y) {
    asm volatile("red.global.add.v2.f32 [%0], {%1,%2};"
                 :: "l"(p), "f"(x), "f"(y) : "memory");
}
__device__ __forceinline__ void red_add_f(float* p, float v) {
    asm volatile("red.global.add.f32 [%0], %1;" :: "l"(p), "f"(v) : "memory");
}

// f32x2 packed-FMA helpers (Blackwell sm_100+)
__device__ __forceinline__ unsigned long long pack2(float x, float y) {
    unsigned long long r;
    asm("mov.b64 %0, {%1, %2};" : "=l"(r) : "f"(x), "f"(y));
    return r;
}
__device__ __forceinline__ void ffma2(unsigned long long& d,
                                      unsigned long long a, unsigned long long b) {
    asm("fma.rn.f32x2 %0, %1, %2, %0;" : "+l"(d) : "l"(a), "l"(b));
}
__device__ __forceinline__ float2 unpack2(unsigned long long v) {
    float2 f;
    asm("mov.b64 {%0, %1}, %2;" : "=f"(f.x), "=f"(f.y) : "l"(v));
    return f;
}

// ---------------------------------------------------------------------------
// K0: zero hin/hout/min/mout/out in one grid-stride launch
__global__ void zero_all_kernel(float4* __restrict__ hin, float4* __restrict__ hout,
                                float4* __restrict__ min_, float4* __restrict__ mout_,
                                float4* __restrict__ out) {
    const int n_h = (NCH * DIM) / 4;
    const int n_m = (NCH * 32) / 4;
    const int n_o = (NR * DIM) / 4;
    float4 z = make_float4(0.f, 0.f, 0.f, 0.f);
    int stride = gridDim.x * blockDim.x;
    for (int i = blockIdx.x * blockDim.x + threadIdx.x; i < n_h; i += stride) {
        hin[i] = z; hout[i] = z;
    }
    for (int i = blockIdx.x * blockDim.x + threadIdx.x; i < n_m; i += stride) {
        min_[i] = z; mout_[i] = z;
    }
    for (int i = blockIdx.x * blockDim.x + threadIdx.x; i < n_o; i += stride) {
        out[i] = z;
    }
}

// ---------------------------------------------------------------------------
// K1: scatter-add h rows along edges: acc[dst[e]] += h[src[e]]  (64 floats/row)
// one thread per (edge, float4-chunk): 16 chunks per edge. Two edge lists in
// one launch (hin via list0, hout via list1).
__global__ void scatter_h_kernel(const int* __restrict__ src0, const int* __restrict__ dst0,
                                 const int* __restrict__ src1, const int* __restrict__ dst1,
                                 const float* __restrict__ h,
                                 float* __restrict__ acc0, float* __restrict__ acc1) {
    int tid = blockIdx.x * blockDim.x + threadIdx.x;
    int e = tid >> 4;
    int c = tid & 15;
    const int* src; const int* dst; float* acc;
    if (e < ERC) { src = src0; dst = dst0; acc = acc0; }
    else if (e < 2 * ERC) { e -= ERC; src = src1; dst = dst1; acc = acc1; }
    else return;
    int s = src[e];
    int d = dst[e];
    float4 v = *(const float4*)(h + (size_t)s * DIM + c * 4);
    red_add_v4(acc + (size_t)d * DIM + c * 4, v);
}

// ---------------------------------------------------------------------------
// K2: e = h_packet @ W_p^T + b_p   (M=16384, N=2048, K=64), output fp16.
// 128x128 tile, 256 threads, 8x8 per thread; inner product with packed
// f32x2 FMA (accumulators pair k-columns).
__global__ void gemm_e_kernel(const float* __restrict__ A,   // [NP, 64]
                              const float* __restrict__ B,   // [EN, 64]
                              const float* __restrict__ bias,// [EN]
                              __half* __restrict__ C) {      // [NP, EN] fp16
    extern __shared__ float sm[];
    float (*As)[128] = (float (*)[128])sm;              // [64][128] k-major
    float (*Bs)[128] = (float (*)[128])(sm + 64 * 128);

    const int t  = threadIdx.x;
    const int m0 = blockIdx.y * 128;
    const int n0 = blockIdx.x * 128;

#pragma unroll
    for (int i = 0; i < 8; i++) {
        int idx = i * 256 + t;       // 0..2047
        int r   = idx & 127;
        int k4  = idx >> 7;          // 0..15
        float4 va = *(const float4*)(A + (size_t)(m0 + r) * DIM + k4 * 4);
        As[k4*4+0][r] = va.x; As[k4*4+1][r] = va.y;
        As[k4*4+2][r] = va.z; As[k4*4+3][r] = va.w;
        float4 vb = *(const float4*)(B + (size_t)(n0 + r) * DIM + k4 * 4);
        Bs[k4*4+0][r] = vb.x; Bs[k4*4+1][r] = vb.y;
        Bs[k4*4+2][r] = vb.z; Bs[k4*4+3][r] = vb.w;
    }
    __syncthreads();

    const int tx = t & 15;   // n
    const int ty = t >> 4;   // m
    unsigned long long acc[8][4];
#pragma unroll
    for (int i = 0; i < 8; i++)
#pragma unroll
        for (int j = 0; j < 4; j++) acc[i][j] = 0ull;

#pragma unroll 16
    for (int k = 0; k < 64; k++) {
        float4 a0 = *(const float4*)&As[k][ty * 4];
        float4 a1 = *(const float4*)&As[k][64 + ty * 4];
        float4 b0 = *(const float4*)&Bs[k][tx * 4];
        float4 b1 = *(const float4*)&Bs[k][64 + tx * 4];
        unsigned long long b2[4] = {pack2(b0.x, b0.y), pack2(b0.z, b0.w),
                                    pack2(b1.x, b1.y), pack2(b1.z, b1.w)};
        float a[8] = {a0.x, a0.y, a0.z, a0.w, a1.x, a1.y, a1.z, a1.w};
#pragma unroll
        for (int i = 0; i < 8; i++) {
            unsigned long long a2 = pack2(a[i], a[i]);
#pragma unroll
            for (int j = 0; j < 4; j++) ffma2(acc[i][j], a2, b2[j]);
        }
    }

    float4 bias0 = *(const float4*)(bias + n0 + tx * 4);
    float4 bias1 = *(const float4*)(bias + n0 + 64 + tx * 4);
    float2 bp[4] = {{bias0.x, bias0.y}, {bias0.z, bias0.w},
                    {bias1.x, bias1.y}, {bias1.z, bias1.w}};
#pragma unroll
    for (int i = 0; i < 8; i++) {
        int m = m0 + ((i < 4) ? (ty * 4 + i) : (64 + ty * 4 + (i - 4)));
        __half* cp = C + (size_t)m * EN + n0;
        __half2 hv[4];
#pragma unroll
        for (int j = 0; j < 4; j++) {
            float2 c = unpack2(acc[i][j]);
            hv[j] = __floats2half2_rn(c.x + bp[j].x, c.y + bp[j].y);
        }
        uint2 w0, w1;
        w0.x = *(unsigned*)&hv[0]; w0.y = *(unsigned*)&hv[1];
        w1.x = *(unsigned*)&hv[2]; w1.y = *(unsigned*)&hv[3];
        *(uint2*)(cp + tx * 4)      = w0;   // cols n0+tx*4 .. +3
        *(uint2*)(cp + 64 + tx * 4) = w1;   // cols n0+64+tx*4 .. +3
    }
}

// ---------------------------------------------------------------------------
// K3: pass edges. One warp per edge (u=pass_src packet, v=pass_dst channel):
//   m_in[v,k]  += sum_d e[u, d*32+k] * h_in[v,d]   (same for m_out with h_out)
// e is fp16. Lane l handles k-pair {2*(l&15), 2*(l&15)+1}; lanes 0-15 cover
// even d, lanes 16-31 odd d; partials combined via shfl_xor(16).
__global__ void pass_kernel(const int* __restrict__ psrc, const int* __restrict__ pdst,
                            const __half2* __restrict__ e2,
                            const float* __restrict__ hin, const float* __restrict__ hout,
                            float* __restrict__ min_, float* __restrict__ mout_) {
    int gtid = blockIdx.x * blockDim.x + threadIdx.x;
    int w    = gtid >> 5;
    int lane = gtid & 31;
    if (w >= EPASS) return;
    int u = psrc[w];
    int v = pdst[w];

    const __half2* ev = e2 + (size_t)u * (EN / 2);
    // lane l holds h[*, l] and h[*, 32+l]
    float hi0 = hin [(size_t)v * DIM + lane];
    float hi1 = hin [(size_t)v * DIM + 32 + lane];
    float ho0 = hout[(size_t)v * DIM + lane];
    float ho1 = hout[(size_t)v * DIM + 32 + lane];

    const int dh = lane >> 4;      // 0: even d, 1: odd d
    float mi0 = 0.f, mi1 = 0.f, mo0 = 0.f, mo1 = 0.f;

#pragma unroll
    for (int dp = 0; dp < 16; dp++) {           // d = 2*dp + dh  in [0,32)
        float2 ef = __half22float2(ev[dp * 32 + lane]);
        int s = 2 * dp + dh;
        float hi = __shfl_sync(0xffffffffu, hi0, s);
        float ho = __shfl_sync(0xffffffffu, ho0, s);
        mi0 += ef.x * hi; mi1 += ef.y * hi;
        mo0 += ef.x * ho; mo1 += ef.y * ho;
    }
#pragma unroll
    for (int dp = 16; dp < 32; dp++) {          // d = 2*dp + dh  in [32,64)
        float2 ef = __half22float2(ev[dp * 32 + lane]);
        int s = 2 * (dp - 16) + dh;
        float hi = __shfl_sync(0xffffffffu, hi1, s);
        float ho = __shfl_sync(0xffffffffu, ho1, s);
        mi0 += ef.x * hi; mi1 += ef.y * hi;
        mo0 += ef.x * ho; mo1 += ef.y * ho;
    }

    // combine even-d (lanes 0-15) with odd-d (lanes 16-31) partials
    mi0 += __shfl_xor_sync(0xffffffffu, mi0, 16);
    mi1 += __shfl_xor_sync(0xffffffffu, mi1, 16);
    mo0 += __shfl_xor_sync(0xffffffffu, mo0, 16);
    mo1 += __shfl_xor_sync(0xffffffffu, mo1, 16);

    int kp = (lane & 15) * 2;
    if (lane < 16) red_add_v2(min_  + (size_t)v * 32 + kp, mi0, mi1);
    else           red_add_v2(mout_ + (size_t)v * 32 + kp, mo0, mo1);
}

// ---------------------------------------------------------------------------
// K4: gather channel -> router into d_out (cols 0..31 from m_in via input edges,
// cols 32..63 from m_out via output_inv edges). Warp per (edge, half).
__global__ void gather_kernel(const int* __restrict__ isrc, const int* __restrict__ idst,
                              const int* __restrict__ oisrc, const int* __restrict__ oidst,
                              const float* __restrict__ min_, const float* __restrict__ mout_,
                              float* __restrict__ out) {
    int gtid = blockIdx.x * blockDim.x + threadIdx.x;
    int w    = gtid >> 5;
    int lane = gtid & 31;
    if (w < ERC) {
        int s = isrc[w], d = idst[w];
        red_add_f(out + (size_t)d * DIM + lane, min_[(size_t)s * 32 + lane]);
    } else if (w < 2 * ERC) {
        int ww = w - ERC;
        int s = oisrc[ww], d = oidst[ww];
        red_add_f(out + (size_t)d * DIM + 32 + lane, mout_[(size_t)s * 32 + lane]);
    }
}

// ---------------------------------------------------------------------------
// K5: relu epilogue on out
__global__ void relu_kernel(float4* __restrict__ out) {
    int i = blockIdx.x * blockDim.x + threadIdx.x;
    float4 v = out[i];
    v.x = fmaxf(v.x, 0.f); v.y = fmaxf(v.y, 0.f);
    v.z = fmaxf(v.z, 0.f); v.w = fmaxf(v.w, 0.f);
    out[i] = v;
}

// ===========================================================================
extern "C" void kernel_launch(void* const* d_in, const int* in_sizes, int n_in,
                              void* d_out, int out_size) {
    const float* h_router       = (const float*)d_in[0];
    const float* h_packet       = (const float*)d_in[1];
    const float* W_p            = (const float*)d_in[2];
    const float* b_p            = (const float*)d_in[3];
    // d_in[4] = W_c, d_in[5] = b_c : dead code in reference
    const int* output_src       = (const int*)d_in[6];
    const int* output_dst       = (const int*)d_in[7];
    const int* input_inv_src    = (const int*)d_in[8];
    const int* input_inv_dst    = (const int*)d_in[9];
    const int* pass_src         = (const int*)d_in[10];
    const int* pass_dst         = (const int*)d_in[11];
    const int* input_src        = (const int*)d_in[12];
    const int* input_dst        = (const int*)d_in[13];
    const int* output_inv_src   = (const int*)d_in[14];
    const int* output_inv_dst   = (const int*)d_in[15];
    float* out = (float*)d_out;

    __half* p_e;
    float *p_hin, *p_hout, *p_min, *p_mout;
    cudaGetSymbolAddress((void**)&p_e,    g_e);
    cudaGetSymbolAddress((void**)&p_hin,  g_hin);
    cudaGetSymbolAddress((void**)&p_hout, g_hout);
    cudaGetSymbolAddress((void**)&p_min,  g_min);
    cudaGetSymbolAddress((void**)&p_mout, g_mout);

    cudaFuncSetAttribute(gemm_e_kernel,
                         cudaFuncAttributeMaxDynamicSharedMemorySize, 65536);

    // zero accumulators + output (one launch)
    zero_all_kernel<<<2048, 256>>>((float4*)p_hin, (float4*)p_hout,
                                   (float4*)p_min, (float4*)p_mout, (float4*)out);

    // router -> channel scatter-adds (both edge lists, one launch)
    scatter_h_kernel<<<(2 * ERC * 16) / 256, 256>>>(
        output_src, output_dst, input_inv_src, input_inv_dst,
        h_router, p_hin, p_hout);

    // e = h_packet @ W_p^T + b_p  (fp16 out)
    {
        dim3 grid(EN / 128, NP / 128);  // (16, 128)
        gemm_e_kernel<<<grid, 256, 65536>>>(h_packet, W_p, b_p, p_e);
    }

    // pass edges: warp per edge
    pass_kernel<<<(EPASS * 32) / 256, 256>>>(pass_src, pass_dst, (const __half2*)p_e,
                                             p_hin, p_hout, p_min, p_mout);

    // channel -> router gathers into out
    gather_kernel<<<(2 * ERC * 32) / 256, 256>>>(input_src, input_dst,
                                                 output_inv_src, output_inv_dst,
                                                 p_min, p_mout, out);

    // relu epilogue
    relu_kernel<<<(NR * DIM) / (4 * 256), 256>>>((float4*)out);
}

// round 4
// speedup vs baseline: 1.8821x; 1.5425x over previous
#include <cuda_runtime.h>
#include <cuda_fp16.h>
#include <cstdint>
#include <cstddef>

// Problem constants (fixed by the dataset)
#define NR    16384
#define NCH   65536
#define NP    16384
#define DIM   64
#define ERC   65536
#define EPASS 65536
#define EN    2048   // D*D/2

// Device scratch (allocation-free rule: __device__ globals)
__device__ __half g_e  [(size_t)NP  * EN];   // 64 MB: per-packet message matrices (fp16)
__device__ float g_hin [(size_t)NCH * DIM];  // 16 MB
__device__ float g_hout[(size_t)NCH * DIM];  // 16 MB
__device__ float g_min [(size_t)NCH * 32];   // 8 MB
__device__ float g_mout[(size_t)NCH * 32];   // 8 MB

__device__ __forceinline__ void red_add_v4(float* p, float4 v) {
    asm volatile("red.global.add.v4.f32 [%0], {%1,%2,%3,%4};"
                 :: "l"(p), "f"(v.x), "f"(v.y), "f"(v.z), "f"(v.w) : "memory");
}
__device__ __forceinline__ void red_add_v2(float* p, float x, float y) {
    asm volatile("red.global.add.v2.f32 [%0], {%1,%2};"
                 :: "l"(p), "f"(x), "f"(y) : "memory");
}
__device__ __forceinline__ void red_add_f(float* p, float v) {
    asm volatile("red.global.add.f32 [%0], %1;" :: "l"(p), "f"(v) : "memory");
}
__device__ __forceinline__ uint32_t smem_u32(const void* p) {
    return (uint32_t)__cvta_generic_to_shared(p);
}

// ---------------------------------------------------------------------------
// K0: zero hin/hout/min/mout/out in one grid-stride launch
__global__ void zero_all_kernel(float4* __restrict__ hin, float4* __restrict__ hout,
                                float4* __restrict__ min_, float4* __restrict__ mout_,
                                float4* __restrict__ out) {
    const int n_h = (NCH * DIM) / 4;
    const int n_m = (NCH * 32) / 4;
    const int n_o = (NR * DIM) / 4;
    float4 z = make_float4(0.f, 0.f, 0.f, 0.f);
    int stride = gridDim.x * blockDim.x;
    for (int i = blockIdx.x * blockDim.x + threadIdx.x; i < n_h; i += stride) {
        hin[i] = z; hout[i] = z;
    }
    for (int i = blockIdx.x * blockDim.x + threadIdx.x; i < n_m; i += stride) {
        min_[i] = z; mout_[i] = z;
    }
    for (int i = blockIdx.x * blockDim.x + threadIdx.x; i < n_o; i += stride) {
        out[i] = z;
    }
}

// ---------------------------------------------------------------------------
// K1: scatter-add h rows along edges: acc[dst[e]] += h[src[e]]  (64 floats/row)
// one thread per (edge, float4-chunk): 16 chunks per edge. Two edge lists in
// one launch (hin via list0, hout via list1).
__global__ void scatter_h_kernel(const int* __restrict__ src0, const int* __restrict__ dst0,
                                 const int* __restrict__ src1, const int* __restrict__ dst1,
                                 const float* __restrict__ h,
                                 float* __restrict__ acc0, float* __restrict__ acc1) {
    int tid = blockIdx.x * blockDim.x + threadIdx.x;
    int e = tid >> 4;
    int c = tid & 15;
    const int* src; const int* dst; float* acc;
    if (e < ERC) { src = src0; dst = dst0; acc = acc0; }
    else if (e < 2 * ERC) { e -= ERC; src = src1; dst = dst1; acc = acc1; }
    else return;
    int s = src[e];
    int d = dst[e];
    float4 v = *(const float4*)(h + (size_t)s * DIM + c * 4);
    red_add_v4(acc + (size_t)d * DIM + c * 4, v);
}

// ---------------------------------------------------------------------------
// K2: e = h_packet @ W_p^T + b_p   (M=16384, N=2048, K=64), fp16 out.
// Tensor-core version: convert A/B to fp16 in XOR-swizzled smem, ldmatrix.x4,
// mma.sync.m16n8k16 with fp32 accumulate. 128x128 tile, 8 warps (2m x 4n),
// warp tile 64x32, K=64 in 4 k-steps, single stage (no pipeline needed).
__global__ void __launch_bounds__(256) gemm_e_hmma(
        const float* __restrict__ A,    // [NP, 64]
        const float* __restrict__ B,    // [EN, 64]
        const float* __restrict__ bias, // [EN]
        __half* __restrict__ C) {       // [NP, EN]
    __shared__ __align__(16) __half As[128 * 64];
    __shared__ __align__(16) __half Bs[128 * 64];
    const int t  = threadIdx.x;
    const int m0 = blockIdx.y * 128;
    const int n0 = blockIdx.x * 128;

    // load + fp32->fp16 convert; 1024 16B-chunks per tile, swizzle chunk^(row&7)
    {
        const float* G0 = A + (size_t)m0 * DIM;
        const float* G1 = B + (size_t)n0 * DIM;
#pragma unroll
        for (int i = 0; i < 4; i++) {
            int idx = i * 256 + t;      // 0..1023
            int r = idx >> 3, ch = idx & 7;
            int pch = ch ^ (r & 7);
            {
                const float4* gp = (const float4*)(G0 + (size_t)r * DIM + ch * 8);
                float4 lo = gp[0], hi = gp[1];
                __half2 h0 = __floats2half2_rn(lo.x, lo.y);
                __half2 h1 = __floats2half2_rn(lo.z, lo.w);
                __half2 h2 = __floats2half2_rn(hi.x, hi.y);
                __half2 h3 = __floats2half2_rn(hi.z, hi.w);
                uint4 v = make_uint4(*(unsigned*)&h0, *(unsigned*)&h1,
                                     *(unsigned*)&h2, *(unsigned*)&h3);
                *(uint4*)(As + r * 64 + pch * 8) = v;
            }
            {
                const float4* gp = (const float4*)(G1 + (size_t)r * DIM + ch * 8);
                float4 lo = gp[0], hi = gp[1];
                __half2 h0 = __floats2half2_rn(lo.x, lo.y);
                __half2 h1 = __floats2half2_rn(lo.z, lo.w);
                __half2 h2 = __floats2half2_rn(hi.x, hi.y);
                __half2 h3 = __floats2half2_rn(hi.z, hi.w);
                uint4 v = make_uint4(*(unsigned*)&h0, *(unsigned*)&h1,
                                     *(unsigned*)&h2, *(unsigned*)&h3);
                *(uint4*)(Bs + r * 64 + pch * 8) = v;
            }
        }
    }
    __syncthreads();

    const int wid  = t >> 5, lane = t & 31;
    const int mbase = (wid >> 2) * 64;   // warp_m in {0,1}
    const int nbase = (wid & 3) * 32;    // warp_n in {0..3}

    float acc[4][4][4];
#pragma unroll
    for (int mt = 0; mt < 4; mt++)
#pragma unroll
        for (int nt = 0; nt < 4; nt++)
#pragma unroll
            for (int j = 0; j < 4; j++) acc[mt][nt][j] = 0.f;

#pragma unroll
    for (int ks = 0; ks < 4; ks++) {
        uint32_t a[4][4], bf[2][4];
        const int lrow = lane & 15;
        const int lch  = 2 * ks + (lane >> 4);
#pragma unroll
        for (int mt = 0; mt < 4; mt++) {
            int r = mbase + mt * 16 + lrow;
            uint32_t addr = smem_u32(As + r * 64 + (lch ^ (r & 7)) * 8);
            asm volatile("ldmatrix.sync.aligned.m8n8.x4.shared.b16 {%0,%1,%2,%3}, [%4];"
                : "=r"(a[mt][0]), "=r"(a[mt][1]), "=r"(a[mt][2]), "=r"(a[mt][3])
                : "r"(addr));
        }
#pragma unroll
        for (int np = 0; np < 2; np++) {
            int r = nbase + np * 16 + lrow;
            uint32_t addr = smem_u32(Bs + r * 64 + (lch ^ (r & 7)) * 8);
            asm volatile("ldmatrix.sync.aligned.m8n8.x4.shared.b16 {%0,%1,%2,%3}, [%4];"
                : "=r"(bf[np][0]), "=r"(bf[np][1]), "=r"(bf[np][2]), "=r"(bf[np][3])
                : "r"(addr));
        }
#pragma unroll
        for (int mt = 0; mt < 4; mt++)
#pragma unroll
            for (int nt = 0; nt < 4; nt++) {
                uint32_t b0 = bf[nt >> 1][nt & 1];
                uint32_t b1 = bf[nt >> 1][2 + (nt & 1)];
                asm volatile(
                    "mma.sync.aligned.m16n8k16.row.col.f32.f16.f16.f32 "
                    "{%0,%1,%2,%3}, {%4,%5,%6,%7}, {%8,%9}, {%0,%1,%2,%3};"
                    : "+f"(acc[mt][nt][0]), "+f"(acc[mt][nt][1]),
                      "+f"(acc[mt][nt][2]), "+f"(acc[mt][nt][3])
                    : "r"(a[mt][0]), "r"(a[mt][1]), "r"(a[mt][2]), "r"(a[mt][3]),
                      "r"(b0), "r"(b1));
            }
    }

    // epilogue: add bias, convert to fp16, store
    const int row_l = lane >> 2;
    const int col_l = (lane & 3) * 2;
#pragma unroll
    for (int mt = 0; mt < 4; mt++) {
        int m = m0 + mbase + mt * 16 + row_l;
#pragma unroll
        for (int nt = 0; nt < 4; nt++) {
            int n = n0 + nbase + nt * 8 + col_l;
            float2 bv = *(const float2*)(bias + n);
            __half2 h01 = __floats2half2_rn(acc[mt][nt][0] + bv.x,
                                            acc[mt][nt][1] + bv.y);
            __half2 h23 = __floats2half2_rn(acc[mt][nt][2] + bv.x,
                                            acc[mt][nt][3] + bv.y);
            *(__half2*)(C + (size_t)m * EN + n)       = h01;
            *(__half2*)(C + (size_t)(m + 8) * EN + n) = h23;
        }
    }
}

// ---------------------------------------------------------------------------
// K3: pass edges. One warp per edge (u=pass_src packet, v=pass_dst channel):
//   m_in[v,k]  += sum_d e[u, d*32+k] * h_in[v,d]   (same for m_out with h_out)
// e is fp16. Lane l handles k-pair {2*(l&15), 2*(l&15)+1}; lanes 0-15 cover
// even d, lanes 16-31 odd d; partials combined via shfl_xor(16).
__global__ void pass_kernel(const int* __restrict__ psrc, const int* __restrict__ pdst,
                            const __half2* __restrict__ e2,
                            const float* __restrict__ hin, const float* __restrict__ hout,
                            float* __restrict__ min_, float* __restrict__ mout_) {
    int gtid = blockIdx.x * blockDim.x + threadIdx.x;
    int w    = gtid >> 5;
    int lane = gtid & 31;
    if (w >= EPASS) return;
    int u = psrc[w];
    int v = pdst[w];

    const __half2* ev = e2 + (size_t)u * (EN / 2);
    float hi0 = hin [(size_t)v * DIM + lane];
    float hi1 = hin [(size_t)v * DIM + 32 + lane];
    float ho0 = hout[(size_t)v * DIM + lane];
    float ho1 = hout[(size_t)v * DIM + 32 + lane];

    const int dh = lane >> 4;      // 0: even d, 1: odd d
    float mi0 = 0.f, mi1 = 0.f, mo0 = 0.f, mo1 = 0.f;

#pragma unroll
    for (int dp = 0; dp < 16; dp++) {           // d = 2*dp + dh  in [0,32)
        float2 ef = __half22float2(ev[dp * 32 + lane]);
        int s = 2 * dp + dh;
        float hi = __shfl_sync(0xffffffffu, hi0, s);
        float ho = __shfl_sync(0xffffffffu, ho0, s);
        mi0 += ef.x * hi; mi1 += ef.y * hi;
        mo0 += ef.x * ho; mo1 += ef.y * ho;
    }
#pragma unroll
    for (int dp = 16; dp < 32; dp++) {          // d = 2*dp + dh  in [32,64)
        float2 ef = __half22float2(ev[dp * 32 + lane]);
        int s = 2 * (dp - 16) + dh;
        float hi = __shfl_sync(0xffffffffu, hi1, s);
        float ho = __shfl_sync(0xffffffffu, ho1, s);
        mi0 += ef.x * hi; mi1 += ef.y * hi;
        mo0 += ef.x * ho; mo1 += ef.y * ho;
    }

    mi0 += __shfl_xor_sync(0xffffffffu, mi0, 16);
    mi1 += __shfl_xor_sync(0xffffffffu, mi1, 16);
    mo0 += __shfl_xor_sync(0xffffffffu, mo0, 16);
    mo1 += __shfl_xor_sync(0xffffffffu, mo1, 16);

    int kp = (lane & 15) * 2;
    if (lane < 16) red_add_v2(min_  + (size_t)v * 32 + kp, mi0, mi1);
    else           red_add_v2(mout_ + (size_t)v * 32 + kp, mo0, mo1);
}

// ---------------------------------------------------------------------------
// K4: gather channel -> router into d_out (cols 0..31 from m_in via input edges,
// cols 32..63 from m_out via output_inv edges). Warp per (edge, half).
__global__ void gather_kernel(const int* __restrict__ isrc, const int* __restrict__ idst,
                              const int* __restrict__ oisrc, const int* __restrict__ oidst,
                              const float* __restrict__ min_, const float* __restrict__ mout_,
                              float* __restrict__ out) {
    int gtid = blockIdx.x * blockDim.x + threadIdx.x;
    int w    = gtid >> 5;
    int lane = gtid & 31;
    if (w < ERC) {
        int s = isrc[w], d = idst[w];
        red_add_f(out + (size_t)d * DIM + lane, min_[(size_t)s * 32 + lane]);
    } else if (w < 2 * ERC) {
        int ww = w - ERC;
        int s = oisrc[ww], d = oidst[ww];
        red_add_f(out + (size_t)d * DIM + 32 + lane, mout_[(size_t)s * 32 + lane]);
    }
}

// ---------------------------------------------------------------------------
// K5: relu epilogue on out
__global__ void relu_kernel(float4* __restrict__ out) {
    int i = blockIdx.x * blockDim.x + threadIdx.x;
    float4 v = out[i];
    v.x = fmaxf(v.x, 0.f); v.y = fmaxf(v.y, 0.f);
    v.z = fmaxf(v.z, 0.f); v.w = fmaxf(v.w, 0.f);
    out[i] = v;
}

// ===========================================================================
extern "C" void kernel_launch(void* const* d_in, const int* in_sizes, int n_in,
                              void* d_out, int out_size) {
    const float* h_router       = (const float*)d_in[0];
    const float* h_packet       = (const float*)d_in[1];
    const float* W_p            = (const float*)d_in[2];
    const float* b_p            = (const float*)d_in[3];
    // d_in[4] = W_c, d_in[5] = b_c : dead code in reference
    const int* output_src       = (const int*)d_in[6];
    const int* output_dst       = (const int*)d_in[7];
    const int* input_inv_src    = (const int*)d_in[8];
    const int* input_inv_dst    = (const int*)d_in[9];
    const int* pass_src         = (const int*)d_in[10];
    const int* pass_dst         = (const int*)d_in[11];
    const int* input_src        = (const int*)d_in[12];
    const int* input_dst        = (const int*)d_in[13];
    const int* output_inv_src   = (const int*)d_in[14];
    const int* output_inv_dst   = (const int*)d_in[15];
    float* out = (float*)d_out;

    __half* p_e;
    float *p_hin, *p_hout, *p_min, *p_mout;
    cudaGetSymbolAddress((void**)&p_e,    g_e);
    cudaGetSymbolAddress((void**)&p_hin,  g_hin);
    cudaGetSymbolAddress((void**)&p_hout, g_hout);
    cudaGetSymbolAddress((void**)&p_min,  g_min);
    cudaGetSymbolAddress((void**)&p_mout, g_mout);

    // zero accumulators + output (one launch)
    zero_all_kernel<<<2048, 256>>>((float4*)p_hin, (float4*)p_hout,
                                   (float4*)p_min, (float4*)p_mout, (float4*)out);

    // router -> channel scatter-adds (both edge lists, one launch)
    scatter_h_kernel<<<(2 * ERC * 16) / 256, 256>>>(
        output_src, output_dst, input_inv_src, input_inv_dst,
        h_router, p_hin, p_hout);

    // e = h_packet @ W_p^T + b_p  (tensor cores, fp16 out)
    {
        dim3 grid(EN / 128, NP / 128);  // (16, 128)
        gemm_e_hmma<<<grid, 256>>>(h_packet, W_p, b_p, p_e);
    }

    // pass edges: warp per edge
    pass_kernel<<<(EPASS * 32) / 256, 256>>>(pass_src, pass_dst, (const __half2*)p_e,
                                             p_hin, p_hout, p_min, p_mout);

    // channel -> router gathers into out
    gather_kernel<<<(2 * ERC * 32) / 256, 256>>>(input_src, input_dst,
                                                 output_inv_src, output_inv_dst,
                                                 p_min, p_mout, out);

    // relu epilogue
    relu_kernel<<<(NR * DIM) / (4 * 256), 256>>>((float4*)out);
}